// round 2
// baseline (speedup 1.0000x reference)
#include <cuda_runtime.h>
#include <cstdint>

// ---------------- problem constants ----------------
#define MD   4096
#define KD   4096
#define BSD  8192
#define NTOT 16777216ull

// ---------------- scratch (device globals; no runtime alloc) ----------------
__device__ float   g_w [(size_t)MD * KD];    // raw radius, then normalized tf32-rounded w'
__device__ float   g_xq[(size_t)BSD * KD];   // tf32-rounded x
__device__ double2 g_part[8192];
__device__ float   g_stats[2];               // mean, alpha

__device__ __forceinline__ float tf32_rna(float x) {
    uint32_t u; asm("cvt.rna.tf32.f32 %0, %1;" : "=r"(u) : "f"(x));
    return __uint_as_float(u);
}

// ---------------- 1) Gielis radius + partial sums ----------------
__global__ void __launch_bounds__(256) wr_kernel(const int* __restrict__ hd,
                                                 const float* __restrict__ dna) {
    __shared__ double s1[256], s2[256];
    int t = threadIdx.x;
    float mp = dna[0], a = dna[1], b = dna[2], n1 = dna[3], n2 = dna[4], n3 = dna[5];
    const float C = 2.0f * 3.14159265358979323846f / 16777216.0f;
    float e1 = -1.0f / n1;
    double s = 0.0, q = 0.0;
    size_t base = (size_t)blockIdx.x * 2048;
#pragma unroll
    for (int j = 0; j < 8; j++) {
        size_t i = base + (size_t)j * 256 + t;
        float th  = (float)hd[i] * C;
        float ang = mp * th * 0.25f;
        float sn, cs; sincosf(ang, &sn, &cs);
        float bse = powf(fabsf(cs / a), n2) + powf(fabsf(sn / b), n3);
        float r = powf(bse, e1);
        g_w[i] = r;
        s += (double)r;
        q += (double)r * (double)r;
    }
    s1[t] = s; s2[t] = q; __syncthreads();
    for (int o = 128; o > 0; o >>= 1) {
        if (t < o) { s1[t] += s1[t + o]; s2[t] += s2[t + o]; }
        __syncthreads();
    }
    if (t == 0) { double2 p; p.x = s1[0]; p.y = s2[0]; g_part[blockIdx.x] = p; }
}

// ---------------- 2) final reduction -> mean, alpha ----------------
__global__ void __launch_bounds__(256) red_kernel() {
    __shared__ double s1[256], s2[256];
    int t = threadIdx.x;
    double s = 0.0, q = 0.0;
    for (int i = t; i < 8192; i += 256) { double2 p = g_part[i]; s += p.x; q += p.y; }
    s1[t] = s; s2[t] = q; __syncthreads();
    for (int o = 128; o > 0; o >>= 1) {
        if (t < o) { s1[t] += s1[t + o]; s2[t] += s2[t + o]; }
        __syncthreads();
    }
    if (t == 0) {
        double N = (double)NTOT;
        double mean = s1[0] / N;
        double var  = (s2[0] - s1[0] * s1[0] / N) / (N - 1.0);
        double alpha = (1.0 / 64.0) / (sqrt(var) + 1e-9);   // 1/sqrt(K) folded in
        g_stats[0] = (float)mean;
        g_stats[1] = (float)alpha;
    }
}

// ---------------- 3) normalize w, round to tf32 (in place) ----------------
__global__ void __launch_bounds__(256) normw_kernel() {
    float mean = g_stats[0], al = g_stats[1];
    float4* w4 = reinterpret_cast<float4*>(g_w);
    size_t n = NTOT / 4;
    for (size_t i = (size_t)blockIdx.x * blockDim.x + threadIdx.x; i < n;
         i += (size_t)gridDim.x * blockDim.x) {
        float4 v = w4[i];
        v.x = tf32_rna((v.x - mean) * al);
        v.y = tf32_rna((v.y - mean) * al);
        v.z = tf32_rna((v.z - mean) * al);
        v.w = tf32_rna((v.w - mean) * al);
        w4[i] = v;
    }
}

// ---------------- 4) x -> tf32-rounded copy ----------------
__global__ void __launch_bounds__(256) convx_kernel(const float* __restrict__ x) {
    const float4* xi = reinterpret_cast<const float4*>(x);
    float4* xo = reinterpret_cast<float4*>(g_xq);
    size_t n = (size_t)BSD * KD / 4;
    for (size_t i = (size_t)blockIdx.x * blockDim.x + threadIdx.x; i < n;
         i += (size_t)gridDim.x * blockDim.x) {
        float4 v = xi[i];
        v.x = tf32_rna(v.x); v.y = tf32_rna(v.y);
        v.z = tf32_rna(v.z); v.w = tf32_rna(v.w);
        xo[i] = v;
    }
}

// ---------------- 5) TF32 mma.sync GEMM ----------------
// out[bs, m] = sum_k xq[bs,k] * w'[m,k] + bias[m]
// CTA: 128(bs) x 256(m), 8 warps (2 x 4) of 64x64, BK=32, 4-stage cp.async.
#define BM 128
#define BN 256
#define BK 32
#define KCH (KD / BK)            // 128
#define STAGES 4
#define APAD 4
#define AW (BK + APAD)           // 36 floats per row
#define A_FLOATS (BM * AW)       // 4608
#define B_FLOATS (BN * AW)       // 9216
#define STAGE_FLOATS (A_FLOATS + B_FLOATS)   // 13824
#define SMEM_TOTAL (STAGES * STAGE_FLOATS * 4)  // 221184 bytes

__device__ __forceinline__ void cp16(uint32_t saddr, const float* gaddr) {
    asm volatile("cp.async.cg.shared.global [%0], [%1], 16;" :: "r"(saddr), "l"(gaddr));
}
__device__ __forceinline__ void cp_commit() {
    asm volatile("cp.async.commit_group;" ::: "memory");
}
__device__ __forceinline__ void cp_wait2() {
    asm volatile("cp.async.wait_group 2;" ::: "memory");
}
__device__ __forceinline__ void mma_tf32(float* d, const uint32_t* a, const uint32_t* b) {
    asm volatile("mma.sync.aligned.m16n8k8.row.col.f32.tf32.tf32.f32 "
                 "{%0,%1,%2,%3}, {%4,%5,%6,%7}, {%8,%9}, {%0,%1,%2,%3};"
                 : "+f"(d[0]), "+f"(d[1]), "+f"(d[2]), "+f"(d[3])
                 : "r"(a[0]), "r"(a[1]), "r"(a[2]), "r"(a[3]), "r"(b[0]), "r"(b[1]));
}

__global__ void __launch_bounds__(256, 1) gemm_tf32(const float* __restrict__ bias,
                                                    float* __restrict__ out) {
    extern __shared__ float smf[];
    int tid = threadIdx.x, wid = tid >> 5, lane = tid & 31;
    int wr = wid & 1;            // bs-dim warp row (2)
    int wc = wid >> 1;           // m-dim warp col (4)
    int g = lane >> 2, tig = lane & 3;
    int mBase  = blockIdx.x * BN;
    int bsBase = blockIdx.y * BM;

    // staging addressing: thread covers A rows via j=0..3, B rows via j=0..7
    const float* gA[4]; uint32_t sA[4];
    const float* gB[8]; uint32_t sB[8];
#pragma unroll
    for (int j = 0; j < 4; j++) {
        int i = tid + j * 256, row = i >> 3, seg = i & 7;
        gA[j] = g_xq + (size_t)(bsBase + row) * KD + seg * 4;
        sA[j] = (uint32_t)__cvta_generic_to_shared(smf + row * AW + seg * 4);
    }
#pragma unroll
    for (int j = 0; j < 8; j++) {
        int i = tid + j * 256, row = i >> 3, seg = i & 7;
        gB[j] = g_w + (size_t)(mBase + row) * KD + seg * 4;
        sB[j] = (uint32_t)__cvta_generic_to_shared(smf + A_FLOATS + row * AW + seg * 4);
    }

    // prologue: issue stages 0..2
#pragma unroll
    for (int s = 0; s < 3; s++) {
        uint32_t so = (uint32_t)(s * STAGE_FLOATS * 4);
#pragma unroll
        for (int j = 0; j < 4; j++) cp16(sA[j] + so, gA[j] + s * BK);
#pragma unroll
        for (int j = 0; j < 8; j++) cp16(sB[j] + so, gB[j] + s * BK);
        cp_commit();
    }

    float acc[4][8][4];
#pragma unroll
    for (int mt = 0; mt < 4; mt++)
#pragma unroll
        for (int nt = 0; nt < 8; nt++)
#pragma unroll
            for (int v = 0; v < 4; v++) acc[mt][nt][v] = 0.0f;

    for (int c = 0; c < KCH; c++) {
        cp_wait2();
        __syncthreads();

        // issue stage c+3
        int c3 = c + 3;
        if (c3 < KCH) {
            uint32_t so = (uint32_t)((c3 & 3) * STAGE_FLOATS * 4);
#pragma unroll
            for (int j = 0; j < 4; j++) cp16(sA[j] + so, gA[j] + c3 * BK);
#pragma unroll
            for (int j = 0; j < 8; j++) cp16(sB[j] + so, gB[j] + c3 * BK);
        }
        cp_commit();

        const float* As = smf + (c & 3) * STAGE_FLOATS;
        const float* Bs = As + A_FLOATS;
#pragma unroll
        for (int ks = 0; ks < 4; ks++) {
            int k0 = ks * 8;
            uint32_t af[4][4];
#pragma unroll
            for (int mt = 0; mt < 4; mt++) {
                const float* ap = As + (wr * 64 + mt * 16 + g) * AW + k0 + tig;
                af[mt][0] = __float_as_uint(ap[0]);
                af[mt][1] = __float_as_uint(ap[8 * AW]);
                af[mt][2] = __float_as_uint(ap[4]);
                af[mt][3] = __float_as_uint(ap[8 * AW + 4]);
            }
            uint32_t bf[8][2];
#pragma unroll
            for (int nt = 0; nt < 8; nt++) {
                const float* bp = Bs + (wc * 64 + nt * 8 + g) * AW + k0 + tig;
                bf[nt][0] = __float_as_uint(bp[0]);
                bf[nt][1] = __float_as_uint(bp[4]);
            }
#pragma unroll
            for (int mt = 0; mt < 4; mt++)
#pragma unroll
                for (int nt = 0; nt < 8; nt++)
                    mma_tf32(acc[mt][nt], af[mt], bf[nt]);
        }
        __syncthreads();
    }

    // epilogue: acc + bias -> out
#pragma unroll
    for (int nt = 0; nt < 8; nt++) {
        int col = mBase + wc * 64 + nt * 8 + 2 * tig;
        float2 bv = *reinterpret_cast<const float2*>(bias + col);
#pragma unroll
        for (int mt = 0; mt < 4; mt++) {
            int r0 = bsBase + wr * 64 + mt * 16 + g;
            float2 o0, o1;
            o0.x = acc[mt][nt][0] + bv.x;
            o0.y = acc[mt][nt][1] + bv.y;
            o1.x = acc[mt][nt][2] + bv.x;
            o1.y = acc[mt][nt][3] + bv.y;
            *reinterpret_cast<float2*>(out + (size_t)r0 * MD + col) = o0;
            *reinterpret_cast<float2*>(out + (size_t)(r0 + 8) * MD + col) = o1;
        }
    }
}

// ---------------- launch ----------------
extern "C" void kernel_launch(void* const* d_in, const int* in_sizes, int n_in,
                              void* d_out, int out_size) {
    const float* x    = (const float*)d_in[0];
    const float* dna  = (const float*)d_in[1];
    const float* bias = (const float*)d_in[2];
    const int*   hd   = (const int*)d_in[3];

    wr_kernel<<<8192, 256>>>(hd, dna);
    red_kernel<<<1, 256>>>();
    normw_kernel<<<2048, 256>>>();
    convx_kernel<<<4096, 256>>>(x);

    cudaFuncSetAttribute(gemm_tf32, cudaFuncAttributeMaxDynamicSharedMemorySize, SMEM_TOTAL);
    dim3 grid(MD / BN, BSD / BM);   // (16, 64), m-fastest
    gemm_tf32<<<grid, 256, SMEM_TOTAL>>>(bias, (float*)d_out);
}

// round 3
// speedup vs baseline: 1.0062x; 1.0062x over previous
#include <cuda_runtime.h>
#include <cstdint>

// ---------------- problem constants ----------------
#define MD   4096
#define KD   4096
#define BSD  8192
#define NTOT 16777216ull
#define NLUT 65536              // interp intervals; NLUT+1 knots

// ---------------- scratch (device globals; no runtime alloc) ----------------
__device__ float   g_w [(size_t)MD * KD];    // normalized tf32-rounded w'
__device__ float   g_lut[NLUT + 1];          // r(ang) knots
__device__ double2 g_part[8192];
__device__ float   g_stats[2];               // mean, alpha

__device__ __forceinline__ float tf32_rna_f(float x) {
    uint32_t u; asm("cvt.rna.tf32.f32 %0, %1;" : "=r"(u) : "f"(x));
    return __uint_as_float(u);
}
__device__ __forceinline__ uint32_t tf32_rna_u(float x) {
    uint32_t u; asm("cvt.rna.tf32.f32 %0, %1;" : "=r"(u) : "f"(x));
    return u;
}

// angle span: ang = mp * theta * 0.25, theta in [0, 2pi * (2^24-1)/2^24]
__device__ __forceinline__ float ang_span(float mp) {
    return mp * 2.0f * 3.14159265358979323846f * 0.25f;   // covers d = 2^24 (inclusive bound)
}

// ---------------- 0) build r(ang) LUT (accurate path, 65537 knots) ----------
__global__ void __launch_bounds__(256) lut_kernel(const float* __restrict__ dna) {
    int i = blockIdx.x * blockDim.x + threadIdx.x;
    if (i > NLUT) return;
    float mp = dna[0], a = dna[1], b = dna[2], n1 = dna[3], n2 = dna[4], n3 = dna[5];
    float span = ang_span(mp);
    float ang = span * ((float)i / (float)NLUT);
    float sn, cs; sincosf(ang, &sn, &cs);
    float bse = powf(fabsf(cs / a), n2) + powf(fabsf(sn / b), n3);
    g_lut[i] = powf(bse, -1.0f / n1);
}

// shared LUT eval: d (int) -> r
__device__ __forceinline__ float lut_r(int d, float k1) {
    float u = (float)d * k1;                  // index coordinate in [0, NLUT]
    int i = (int)u;
    i = i < (NLUT - 1) ? i : (NLUT - 1);
    float f = u - (float)i;
    float v0 = g_lut[i], v1 = g_lut[i + 1];
    return v0 + f * (v1 - v0);
}

// ---------------- 1) pass 1: sums of r (no store) ----------------
__global__ void __launch_bounds__(256) sum_kernel(const int* __restrict__ hd,
                                                  const float* __restrict__ dna) {
    __shared__ double s1[256], s2[256];
    int t = threadIdx.x;
    float mp = dna[0];
    // d in [0, 2^24); ang = d * mp*2pi/2^24*0.25 ; index = ang/span*NLUT = d * NLUT / 2^24
    float k1 = (float)NLUT / 16777216.0f;   // exact power of two ratio: 2^-8
    (void)mp;
    double s = 0.0, q = 0.0;
    size_t base = (size_t)blockIdx.x * 2048;
#pragma unroll
    for (int j = 0; j < 8; j++) {
        size_t i = base + (size_t)j * 256 + t;
        float r = lut_r(hd[i], k1);
        s += (double)r;
        q += (double)r * (double)r;
    }
    s1[t] = s; s2[t] = q; __syncthreads();
    for (int o = 128; o > 0; o >>= 1) {
        if (t < o) { s1[t] += s1[t + o]; s2[t] += s2[t + o]; }
        __syncthreads();
    }
    if (t == 0) { double2 p; p.x = s1[0]; p.y = s2[0]; g_part[blockIdx.x] = p; }
}

// ---------------- 2) final reduction -> mean, alpha ----------------
__global__ void __launch_bounds__(256) red_kernel() {
    __shared__ double s1[256], s2[256];
    int t = threadIdx.x;
    double s = 0.0, q = 0.0;
    for (int i = t; i < 8192; i += 256) { double2 p = g_part[i]; s += p.x; q += p.y; }
    s1[t] = s; s2[t] = q; __syncthreads();
    for (int o = 128; o > 0; o >>= 1) {
        if (t < o) { s1[t] += s1[t + o]; s2[t] += s2[t + o]; }
        __syncthreads();
    }
    if (t == 0) {
        double N = (double)NTOT;
        double mean = s1[0] / N;
        double var  = (s2[0] - s1[0] * s1[0] / N) / (N - 1.0);
        double alpha = (1.0 / 64.0) / (sqrt(var) + 1e-9);   // 1/sqrt(K) folded in
        g_stats[0] = (float)mean;
        g_stats[1] = (float)alpha;
    }
}

// ---------------- 3) pass 2: recompute r, normalize, round, store w' -------
__global__ void __launch_bounds__(256) wgen_kernel(const int* __restrict__ hd) {
    float mean = g_stats[0], al = g_stats[1];
    float k1 = (float)NLUT / 16777216.0f;
    int t = threadIdx.x;
    size_t base = (size_t)blockIdx.x * 2048;
#pragma unroll
    for (int j = 0; j < 8; j++) {
        size_t i = base + (size_t)j * 256 + t;
        float r = lut_r(hd[i], k1);
        g_w[i] = tf32_rna_f((r - mean) * al);
    }
}

// ---------------- 4) TF32 mma.sync GEMM ----------------
// out[bs, m] = sum_k x[bs,k] * w'[m,k] + bias[m]   (A rounded to tf32 in-register)
#define BM 128
#define BN 256
#define BK 32
#define KCH (KD / BK)            // 128
#define STAGES 4
#define APAD 4
#define AW (BK + APAD)           // 36
#define A_FLOATS (BM * AW)
#define B_FLOATS (BN * AW)
#define STAGE_FLOATS (A_FLOATS + B_FLOATS)
#define SMEM_TOTAL (STAGES * STAGE_FLOATS * 4)  // 221184 bytes

__device__ __forceinline__ void cp16(uint32_t saddr, const float* gaddr) {
    asm volatile("cp.async.cg.shared.global [%0], [%1], 16;" :: "r"(saddr), "l"(gaddr));
}
__device__ __forceinline__ void cp_commit() {
    asm volatile("cp.async.commit_group;" ::: "memory");
}
__device__ __forceinline__ void cp_wait2() {
    asm volatile("cp.async.wait_group 2;" ::: "memory");
}
__device__ __forceinline__ void mma_tf32(float* d, const uint32_t* a, const uint32_t* b) {
    asm volatile("mma.sync.aligned.m16n8k8.row.col.f32.tf32.tf32.f32 "
                 "{%0,%1,%2,%3}, {%4,%5,%6,%7}, {%8,%9}, {%0,%1,%2,%3};"
                 : "+f"(d[0]), "+f"(d[1]), "+f"(d[2]), "+f"(d[3])
                 : "r"(a[0]), "r"(a[1]), "r"(a[2]), "r"(a[3]), "r"(b[0]), "r"(b[1]));
}

__global__ void __launch_bounds__(256, 1) gemm_tf32(const float* __restrict__ x,
                                                    const float* __restrict__ bias,
                                                    float* __restrict__ out) {
    extern __shared__ float smf[];
    int tid = threadIdx.x, wid = tid >> 5, lane = tid & 31;
    int wr = wid & 1;
    int wc = wid >> 1;
    int g = lane >> 2, tig = lane & 3;
    int mBase  = blockIdx.x * BN;
    int bsBase = blockIdx.y * BM;

    const float* gA[4]; uint32_t sA[4];
    const float* gB[8]; uint32_t sB[8];
#pragma unroll
    for (int j = 0; j < 4; j++) {
        int i = tid + j * 256, row = i >> 3, seg = i & 7;
        gA[j] = x + (size_t)(bsBase + row) * KD + seg * 4;
        sA[j] = (uint32_t)__cvta_generic_to_shared(smf + row * AW + seg * 4);
    }
#pragma unroll
    for (int j = 0; j < 8; j++) {
        int i = tid + j * 256, row = i >> 3, seg = i & 7;
        gB[j] = g_w + (size_t)(mBase + row) * KD + seg * 4;
        sB[j] = (uint32_t)__cvta_generic_to_shared(smf + A_FLOATS + row * AW + seg * 4);
    }

    // prologue: stages 0..2
#pragma unroll
    for (int s = 0; s < 3; s++) {
        uint32_t so = (uint32_t)(s * STAGE_FLOATS * 4);
#pragma unroll
        for (int j = 0; j < 4; j++) cp16(sA[j] + so, gA[j] + s * BK);
#pragma unroll
        for (int j = 0; j < 8; j++) cp16(sB[j] + so, gB[j] + s * BK);
        cp_commit();
    }

    float acc[4][8][4];
#pragma unroll
    for (int mt = 0; mt < 4; mt++)
#pragma unroll
        for (int nt = 0; nt < 8; nt++)
#pragma unroll
            for (int v = 0; v < 4; v++) acc[mt][nt][v] = 0.0f;

    for (int c = 0; c < KCH; c++) {
        cp_wait2();
        __syncthreads();           // also guards slot (c+3)&3 = slot of stage c-1

        int c3 = c + 3;
        if (c3 < KCH) {
            uint32_t so = (uint32_t)((c3 & 3) * STAGE_FLOATS * 4);
#pragma unroll
            for (int j = 0; j < 4; j++) cp16(sA[j] + so, gA[j] + c3 * BK);
#pragma unroll
            for (int j = 0; j < 8; j++) cp16(sB[j] + so, gB[j] + c3 * BK);
        }
        cp_commit();

        const float* As = smf + (c & 3) * STAGE_FLOATS;
        const float* Bs = As + A_FLOATS;
#pragma unroll
        for (int ks = 0; ks < 4; ks++) {
            int k0 = ks * 8;
            uint32_t af[4][4];
#pragma unroll
            for (int mt = 0; mt < 4; mt++) {
                const float* ap = As + (wr * 64 + mt * 16 + g) * AW + k0 + tig;
                af[mt][0] = tf32_rna_u(ap[0]);
                af[mt][1] = tf32_rna_u(ap[8 * AW]);
                af[mt][2] = tf32_rna_u(ap[4]);
                af[mt][3] = tf32_rna_u(ap[8 * AW + 4]);
            }
            uint32_t bf[8][2];
#pragma unroll
            for (int nt = 0; nt < 8; nt++) {
                const float* bp = Bs + (wc * 64 + nt * 8 + g) * AW + k0 + tig;
                bf[nt][0] = __float_as_uint(bp[0]);
                bf[nt][1] = __float_as_uint(bp[4]);
            }
#pragma unroll
            for (int mt = 0; mt < 4; mt++)
#pragma unroll
                for (int nt = 0; nt < 8; nt++)
                    mma_tf32(acc[mt][nt], af[mt], bf[nt]);
        }
    }

    __syncthreads();
#pragma unroll
    for (int nt = 0; nt < 8; nt++) {
        int col = mBase + wc * 64 + nt * 8 + 2 * tig;
        float2 bv = *reinterpret_cast<const float2*>(bias + col);
#pragma unroll
        for (int mt = 0; mt < 4; mt++) {
            int r0 = bsBase + wr * 64 + mt * 16 + g;
            float2 o0, o1;
            o0.x = acc[mt][nt][0] + bv.x;
            o0.y = acc[mt][nt][1] + bv.y;
            o1.x = acc[mt][nt][2] + bv.x;
            o1.y = acc[mt][nt][3] + bv.y;
            *reinterpret_cast<float2*>(out + (size_t)r0 * MD + col) = o0;
            *reinterpret_cast<float2*>(out + (size_t)(r0 + 8) * MD + col) = o1;
        }
    }
}

// ---------------- launch ----------------
extern "C" void kernel_launch(void* const* d_in, const int* in_sizes, int n_in,
                              void* d_out, int out_size) {
    const float* x    = (const float*)d_in[0];
    const float* dna  = (const float*)d_in[1];
    const float* bias = (const float*)d_in[2];
    const int*   hd   = (const int*)d_in[3];

    lut_kernel<<<(NLUT + 1 + 255) / 256, 256>>>(dna);
    sum_kernel<<<8192, 256>>>(hd, dna);
    red_kernel<<<1, 256>>>();
    wgen_kernel<<<8192, 256>>>(hd);

    cudaFuncSetAttribute(gemm_tf32, cudaFuncAttributeMaxDynamicSharedMemorySize, SMEM_TOTAL);
    dim3 grid(MD / BN, BSD / BM);   // (16, 64)
    gemm_tf32<<<grid, 256, SMEM_TOTAL>>>(x, bias, (float*)d_out);
}

// round 4
// speedup vs baseline: 1.0238x; 1.0175x over previous
#include <cuda_runtime.h>
#include <cstdint>

// ---------------- problem constants ----------------
#define MD   4096
#define KD   4096
#define BSD  8192
#define NTOT 16777216ull
#define NLUT 262144              // 2^18 interp intervals; NLUT+1 knots

// ---------------- scratch (device globals; no runtime alloc) ----------------
__device__ float   g_w [(size_t)MD * KD];    // normalized tf32-rounded w'
__device__ float   g_lut[NLUT + 1];
__device__ double2 g_part[8192];
__device__ float   g_stats[2];               // mean, alpha
__device__ int     g_counter;                // zero-init; reset each launch

__device__ __forceinline__ float tf32_rna_f(float x) {
    uint32_t u; asm("cvt.rna.tf32.f32 %0, %1;" : "=r"(u) : "f"(x));
    return __uint_as_float(u);
}
__device__ __forceinline__ uint32_t tf32_rna_u(float x) {
    uint32_t u; asm("cvt.rna.tf32.f32 %0, %1;" : "=r"(u) : "f"(x));
    return u;
}

// ---------------- 0) build r(ang) LUT ----------------
__global__ void __launch_bounds__(256) lut_kernel(const float* __restrict__ dna) {
    int i = blockIdx.x * blockDim.x + threadIdx.x;
    if (i > NLUT) return;
    float mp = dna[0], a = dna[1], b = dna[2], n1 = dna[3], n2 = dna[4], n3 = dna[5];
    float span = mp * 2.0f * 3.14159265358979323846f * 0.25f;
    float ang = span * ((float)i / (float)NLUT);
    float sn, cs; sincosf(ang, &sn, &cs);
    float bse = powf(fabsf(cs / a), n2) + powf(fabsf(sn / b), n3);
    g_lut[i] = powf(bse, -1.0f / n1);
}

// d (int in [0,2^24)) -> r via lerp; index = d * NLUT/2^24 = d/64
__device__ __forceinline__ float lut_r(int d) {
    float u = (float)d * (1.0f / 64.0f);
    int i = (int)u;
    i = i < NLUT ? i : NLUT - 1;
    float f = u - (float)i;
    float v0 = g_lut[i], v1 = g_lut[i + 1];
    return v0 + f * (v1 - v0);
}

// ---------------- 1) sums of r + fused final reduction ----------------
__global__ void __launch_bounds__(256) sum_kernel(const int* __restrict__ hd) {
    __shared__ double s1[256], s2[256];
    __shared__ int lastFlag;
    int t = threadIdx.x;
    double s = 0.0, q = 0.0;
    size_t base = (size_t)blockIdx.x * 2048;
#pragma unroll
    for (int j = 0; j < 8; j++) {
        size_t i = base + (size_t)j * 256 + t;
        float r = lut_r(hd[i]);
        s += (double)r;
        q += (double)r * (double)r;
    }
    s1[t] = s; s2[t] = q; __syncthreads();
    for (int o = 128; o > 0; o >>= 1) {
        if (t < o) { s1[t] += s1[t + o]; s2[t] += s2[t + o]; }
        __syncthreads();
    }
    if (t == 0) {
        double2 p; p.x = s1[0]; p.y = s2[0];
        g_part[blockIdx.x] = p;
        __threadfence();
        int old = atomicAdd(&g_counter, 1);
        lastFlag = (old == gridDim.x - 1) ? 1 : 0;
    }
    __syncthreads();
    if (lastFlag) {
        __threadfence();
        double fs = 0.0, fq = 0.0;
        for (int i = t; i < 8192; i += 256) { double2 p = g_part[i]; fs += p.x; fq += p.y; }
        s1[t] = fs; s2[t] = fq; __syncthreads();
        for (int o = 128; o > 0; o >>= 1) {
            if (t < o) { s1[t] += s1[t + o]; s2[t] += s2[t + o]; }
            __syncthreads();
        }
        if (t == 0) {
            double N = (double)NTOT;
            double mean = s1[0] / N;
            double var  = (s2[0] - s1[0] * s1[0] / N) / (N - 1.0);
            double alpha = (1.0 / 64.0) / (sqrt(var) + 1e-9);  // 1/sqrt(K) folded in
            g_stats[0] = (float)mean;
            g_stats[1] = (float)alpha;
            g_counter = 0;   // reset for next graph replay
        }
    }
}

// ---------------- 2) recompute r, normalize, round, store w' ----------------
__global__ void __launch_bounds__(256) wgen_kernel(const int* __restrict__ hd) {
    float mean = g_stats[0], al = g_stats[1];
    int t = threadIdx.x;
    size_t base = (size_t)blockIdx.x * 2048;
#pragma unroll
    for (int j = 0; j < 8; j++) {
        size_t i = base + (size_t)j * 256 + t;
        float r = lut_r(hd[i]);
        g_w[i] = tf32_rna_f((r - mean) * al);
    }
}

// ---------------- 3) TF32 mma.sync GEMM with ldmatrix ----------------
#define BM 128
#define BN 256
#define BK 32
#define KCH (KD / BK)            // 128
#define STAGES 4
#define APAD 4
#define AW (BK + APAD)           // 36 floats/row -> 144B row stride (LDSM conflict-free)
#define A_FLOATS (BM * AW)
#define B_FLOATS (BN * AW)
#define STAGE_FLOATS (A_FLOATS + B_FLOATS)
#define STAGE_BYTES (STAGE_FLOATS * 4)
#define SMEM_TOTAL (STAGES * STAGE_BYTES)    // 221184

__device__ __forceinline__ void cp16(uint32_t saddr, const float* gaddr) {
    asm volatile("cp.async.cg.shared.global [%0], [%1], 16;" :: "r"(saddr), "l"(gaddr));
}
__device__ __forceinline__ void cp_commit() {
    asm volatile("cp.async.commit_group;" ::: "memory");
}
__device__ __forceinline__ void cp_wait2() {
    asm volatile("cp.async.wait_group 2;" ::: "memory");
}
__device__ __forceinline__ void ldsm4(uint32_t& r0, uint32_t& r1, uint32_t& r2, uint32_t& r3,
                                      uint32_t addr) {
    asm volatile("ldmatrix.sync.aligned.m8n8.x4.shared.b16 {%0,%1,%2,%3}, [%4];"
                 : "=r"(r0), "=r"(r1), "=r"(r2), "=r"(r3) : "r"(addr));
}
__device__ __forceinline__ void mma_tf32(float* d, const uint32_t* a, const uint32_t* b) {
    asm volatile("mma.sync.aligned.m16n8k8.row.col.f32.tf32.tf32.f32 "
                 "{%0,%1,%2,%3}, {%4,%5,%6,%7}, {%8,%9}, {%0,%1,%2,%3};"
                 : "+f"(d[0]), "+f"(d[1]), "+f"(d[2]), "+f"(d[3])
                 : "r"(a[0]), "r"(a[1]), "r"(a[2]), "r"(a[3]), "r"(b[0]), "r"(b[1]));
}

__global__ void __launch_bounds__(256, 1) gemm_tf32(const float* __restrict__ x,
                                                    const float* __restrict__ bias,
                                                    float* __restrict__ out) {
    extern __shared__ float smf[];
    int tid = threadIdx.x, wid = tid >> 5, lane = tid & 31;
    int wr = wid & 1;            // 2 bs-groups of 64
    int wc = wid >> 1;           // 4 m-groups of 64
    int g = lane >> 2, tig = lane & 3;
    int mBase  = blockIdx.x * BN;
    int bsBase = blockIdx.y * BM;

    // cp.async staging: thread -> (row0 + j*32, seg)
    int row0 = tid >> 3, seg = tid & 7;
    const float* gA = x   + (size_t)(bsBase + row0) * KD + seg * 4;
    const float* gB = g_w + (size_t)(mBase  + row0) * KD + seg * 4;
    uint32_t sA0 = (uint32_t)__cvta_generic_to_shared(smf + row0 * AW + seg * 4);
    uint32_t sB0 = (uint32_t)__cvta_generic_to_shared(smf + A_FLOATS + row0 * AW + seg * 4);

    // prologue: stages 0..2
#pragma unroll
    for (int s = 0; s < 3; s++) {
        uint32_t so = (uint32_t)(s * STAGE_BYTES);
#pragma unroll
        for (int j = 0; j < 4; j++) cp16(sA0 + so + j * 32 * AW * 4, gA + s * BK + (size_t)j * 32 * KD);
#pragma unroll
        for (int j = 0; j < 8; j++) cp16(sB0 + so + j * 32 * AW * 4, gB + s * BK + (size_t)j * 32 * KD);
        cp_commit();
    }

    // ldmatrix per-lane addresses (stage-0 base; add stage/k offsets in-loop)
    int mi = lane >> 3, ri = lane & 7;
    uint32_t aAddr[4], bAddr[4];
#pragma unroll
    for (int mt = 0; mt < 4; mt++)
        aAddr[mt] = (uint32_t)__cvta_generic_to_shared(
            smf + (wr * 64 + mt * 16 + (mi & 1) * 8 + ri) * AW + (mi >> 1) * 4);
#pragma unroll
    for (int p = 0; p < 4; p++)
        bAddr[p] = (uint32_t)__cvta_generic_to_shared(
            smf + A_FLOATS + (wc * 64 + (2 * p + (mi >> 1)) * 8 + ri) * AW + (mi & 1) * 4);

    float acc[4][8][4];
#pragma unroll
    for (int mt = 0; mt < 4; mt++)
#pragma unroll
        for (int nt = 0; nt < 8; nt++)
#pragma unroll
            for (int v = 0; v < 4; v++) acc[mt][nt][v] = 0.0f;

    for (int c = 0; c < KCH; c++) {
        cp_wait2();
        __syncthreads();

        int c3 = c + 3;
        if (c3 < KCH) {
            uint32_t so = (uint32_t)((c3 & 3) * STAGE_BYTES);
#pragma unroll
            for (int j = 0; j < 4; j++) cp16(sA0 + so + j * 32 * AW * 4, gA + c3 * BK + (size_t)j * 32 * KD);
#pragma unroll
            for (int j = 0; j < 8; j++) cp16(sB0 + so + j * 32 * AW * 4, gB + c3 * BK + (size_t)j * 32 * KD);
        }
        cp_commit();

        uint32_t stby = (uint32_t)((c & 3) * STAGE_BYTES);
#pragma unroll
        for (int ks = 0; ks < 4; ks++) {
            uint32_t kb = stby + ks * 32;     // ks*8 floats = 32 bytes
            uint32_t af[4][4], bf[8][2];
#pragma unroll
            for (int mt = 0; mt < 4; mt++)
                ldsm4(af[mt][0], af[mt][1], af[mt][2], af[mt][3], aAddr[mt] + kb);
#pragma unroll
            for (int p = 0; p < 4; p++) {
                uint32_t r0, r1, r2, r3;
                ldsm4(r0, r1, r2, r3, bAddr[p] + kb);
                bf[2 * p][0] = r0; bf[2 * p][1] = r1;
                bf[2 * p + 1][0] = r2; bf[2 * p + 1][1] = r3;
            }
#pragma unroll
            for (int mt = 0; mt < 4; mt++)
#pragma unroll
                for (int v = 0; v < 4; v++)
                    af[mt][v] = tf32_rna_u(__uint_as_float(af[mt][v]));
#pragma unroll
            for (int mt = 0; mt < 4; mt++)
#pragma unroll
                for (int nt = 0; nt < 8; nt++)
                    mma_tf32(acc[mt][nt], af[mt], bf[nt]);
        }
    }

    __syncthreads();
#pragma unroll
    for (int nt = 0; nt < 8; nt++) {
        int col = mBase + wc * 64 + nt * 8 + 2 * tig;
        float2 bv = *reinterpret_cast<const float2*>(bias + col);
#pragma unroll
        for (int mt = 0; mt < 4; mt++) {
            int r0 = bsBase + wr * 64 + mt * 16 + g;
            float2 o0, o1;
            o0.x = acc[mt][nt][0] + bv.x;
            o0.y = acc[mt][nt][1] + bv.y;
            o1.x = acc[mt][nt][2] + bv.x;
            o1.y = acc[mt][nt][3] + bv.y;
            *reinterpret_cast<float2*>(out + (size_t)r0 * MD + col) = o0;
            *reinterpret_cast<float2*>(out + (size_t)(r0 + 8) * MD + col) = o1;
        }
    }
}

// ---------------- launch ----------------
extern "C" void kernel_launch(void* const* d_in, const int* in_sizes, int n_in,
                              void* d_out, int out_size) {
    const float* x    = (const float*)d_in[0];
    const float* dna  = (const float*)d_in[1];
    const float* bias = (const float*)d_in[2];
    const int*   hd   = (const int*)d_in[3];

    lut_kernel<<<(NLUT + 1 + 255) / 256, 256>>>(dna);
    sum_kernel<<<8192, 256>>>(hd);
    wgen_kernel<<<8192, 256>>>(hd);

    cudaFuncSetAttribute(gemm_tf32, cudaFuncAttributeMaxDynamicSharedMemorySize, SMEM_TOTAL);
    dim3 grid(MD / BN, BSD / BM);   // (16, 64)
    gemm_tf32<<<grid, 256, SMEM_TOTAL>>>(x, bias, (float*)d_out);
}

// round 5
// speedup vs baseline: 1.6248x; 1.5870x over previous
#include <cuda_runtime.h>
#include <cuda_fp16.h>
#include <cstdint>

// ---------------- problem constants ----------------
#define MD   4096
#define KD   4096
#define BSD  8192
#define NTOT 16777216ull
#define NLUT 262144              // 2^18 intervals

// ---------------- scratch (device globals) ----------------
__device__ __half  g_wh[(size_t)MD * KD];    // normalized fp16 w'
__device__ __half  g_xh[(size_t)BSD * KD];   // fp16 x
__device__ float   g_lut[NLUT + 1];
__device__ double2 g_part[8192];
__device__ float   g_stats[2];
__device__ int     g_counter;

// ---------------- 0) build r(ang) LUT ----------------
__global__ void __launch_bounds__(256) lut_kernel(const float* __restrict__ dna) {
    int i = blockIdx.x * blockDim.x + threadIdx.x;
    if (i > NLUT) return;
    float mp = dna[0], a = dna[1], b = dna[2], n1 = dna[3], n2 = dna[4], n3 = dna[5];
    float span = mp * 2.0f * 3.14159265358979323846f * 0.25f;
    float ang = span * ((float)i / (float)NLUT);
    float sn, cs; sincosf(ang, &sn, &cs);
    float bse = powf(fabsf(cs / a), n2) + powf(fabsf(sn / b), n3);
    g_lut[i] = powf(bse, -1.0f / n1);
}

__device__ __forceinline__ float lut_r(int d) {
    float u = (float)d * (1.0f / 64.0f);     // NLUT/2^24 = 2^-6
    int i = (int)u;
    i = i < NLUT ? i : NLUT - 1;
    float f = u - (float)i;
    float v0 = g_lut[i], v1 = g_lut[i + 1];
    return v0 + f * (v1 - v0);
}

// ---------------- 1) sums of r + fused final reduction ----------------
__global__ void __launch_bounds__(256) sum_kernel(const int* __restrict__ hd) {
    __shared__ double s1[256], s2[256];
    __shared__ int lastFlag;
    int t = threadIdx.x;
    double s = 0.0, q = 0.0;
    size_t base = (size_t)blockIdx.x * 2048;
#pragma unroll
    for (int j = 0; j < 8; j++) {
        size_t i = base + (size_t)j * 256 + t;
        float r = lut_r(hd[i]);
        s += (double)r;
        q += (double)r * (double)r;
    }
    s1[t] = s; s2[t] = q; __syncthreads();
    for (int o = 128; o > 0; o >>= 1) {
        if (t < o) { s1[t] += s1[t + o]; s2[t] += s2[t + o]; }
        __syncthreads();
    }
    if (t == 0) {
        double2 p; p.x = s1[0]; p.y = s2[0];
        g_part[blockIdx.x] = p;
        __threadfence();
        int old = atomicAdd(&g_counter, 1);
        lastFlag = (old == gridDim.x - 1) ? 1 : 0;
    }
    __syncthreads();
    if (lastFlag) {
        __threadfence();
        double fs = 0.0, fq = 0.0;
        for (int i = t; i < 8192; i += 256) { double2 p = g_part[i]; fs += p.x; fq += p.y; }
        s1[t] = fs; s2[t] = fq; __syncthreads();
        for (int o = 128; o > 0; o >>= 1) {
            if (t < o) { s1[t] += s1[t + o]; s2[t] += s2[t + o]; }
            __syncthreads();
        }
        if (t == 0) {
            double N = (double)NTOT;
            double mean = s1[0] / N;
            double var  = (s2[0] - s1[0] * s1[0] / N) / (N - 1.0);
            double alpha = (1.0 / 64.0) / (sqrt(var) + 1e-9);
            g_stats[0] = (float)mean;
            g_stats[1] = (float)alpha;
            g_counter = 0;
        }
    }
}

// ---------------- 2) w' -> fp16 ----------------
__global__ void __launch_bounds__(256) wgen_kernel(const int* __restrict__ hd) {
    float mean = g_stats[0], al = g_stats[1];
    int t = threadIdx.x;
    size_t base = (size_t)blockIdx.x * 2048;
#pragma unroll
    for (int j = 0; j < 8; j++) {
        size_t i = base + (size_t)j * 256 + t;
        float r = lut_r(hd[i]);
        g_wh[i] = __float2half_rn((r - mean) * al);
    }
}

// ---------------- 3) x -> fp16 ----------------
__global__ void __launch_bounds__(256) convx_kernel(const float* __restrict__ x) {
    const float4* xi = reinterpret_cast<const float4*>(x);
    size_t n = (size_t)BSD * KD / 4;
    uint2* xo = reinterpret_cast<uint2*>(g_xh);
    for (size_t i = (size_t)blockIdx.x * blockDim.x + threadIdx.x; i < n;
         i += (size_t)gridDim.x * blockDim.x) {
        float4 v = xi[i];
        __half2 h0 = __floats2half2_rn(v.x, v.y);
        __half2 h1 = __floats2half2_rn(v.z, v.w);
        uint2 o;
        o.x = *reinterpret_cast<uint32_t*>(&h0);
        o.y = *reinterpret_cast<uint32_t*>(&h1);
        xo[i] = o;
    }
}

// ---------------- 4) FP16 mma.sync GEMM ----------------
// out[bs, m] = sum_k xh[bs,k] * wh[m,k] + bias[m]
#define BM 128
#define BN 256
#define BK 32                      // halfs per chunk
#define KCH (KD / BK)              // 128
#define STAGES 4
#define AW 40                      // 32 + 8 pad halfs -> 80B row stride
#define A_HALFS (BM * AW)          // 5120
#define B_HALFS (BN * AW)          // 10240
#define STAGE_HALFS (A_HALFS + B_HALFS)
#define STAGE_BYTES (STAGE_HALFS * 2)          // 30720
#define SMEM_TOTAL (STAGES * STAGE_BYTES)      // 122880

__device__ __forceinline__ void cp16(uint32_t saddr, const void* gaddr) {
    asm volatile("cp.async.cg.shared.global [%0], [%1], 16;" :: "r"(saddr), "l"(gaddr));
}
__device__ __forceinline__ void cp_commit() {
    asm volatile("cp.async.commit_group;" ::: "memory");
}
__device__ __forceinline__ void cp_wait2() {
    asm volatile("cp.async.wait_group 2;" ::: "memory");
}
__device__ __forceinline__ void ldsm4(uint32_t& r0, uint32_t& r1, uint32_t& r2, uint32_t& r3,
                                      uint32_t addr) {
    asm volatile("ldmatrix.sync.aligned.m8n8.x4.shared.b16 {%0,%1,%2,%3}, [%4];"
                 : "=r"(r0), "=r"(r1), "=r"(r2), "=r"(r3) : "r"(addr));
}
__device__ __forceinline__ void mma_f16(float* d, const uint32_t* a, const uint32_t* b) {
    asm volatile("mma.sync.aligned.m16n8k16.row.col.f32.f16.f16.f32 "
                 "{%0,%1,%2,%3}, {%4,%5,%6,%7}, {%8,%9}, {%0,%1,%2,%3};"
                 : "+f"(d[0]), "+f"(d[1]), "+f"(d[2]), "+f"(d[3])
                 : "r"(a[0]), "r"(a[1]), "r"(a[2]), "r"(a[3]), "r"(b[0]), "r"(b[1]));
}

__global__ void __launch_bounds__(256, 1) gemm_f16(const float* __restrict__ bias,
                                                   float* __restrict__ out) {
    extern __shared__ __half smh[];
    int tid = threadIdx.x, wid = tid >> 5, lane = tid & 31;
    int wr = wid & 1;            // 2 bs-groups of 64
    int wc = wid >> 1;           // 4 m-groups of 64
    int g = lane >> 2, tig = lane & 3;
    int mBase  = blockIdx.x * BN;
    int bsBase = blockIdx.y * BM;

    // cp.async staging: 16B segs; A 128x4 segs, B 256x4 segs
    int srow = tid >> 2, sseg = tid & 3;
    const __half* gA = g_xh + (size_t)(bsBase + srow) * KD + sseg * 8;
    const __half* gB = g_wh + (size_t)(mBase  + srow) * KD + sseg * 8;
    uint32_t sA0 = (uint32_t)__cvta_generic_to_shared(smh + srow * AW + sseg * 8);
    uint32_t sB0 = (uint32_t)__cvta_generic_to_shared(smh + A_HALFS + srow * AW + sseg * 8);

    // prologue: stages 0..2
#pragma unroll
    for (int s = 0; s < 3; s++) {
        uint32_t so = (uint32_t)(s * STAGE_BYTES);
#pragma unroll
        for (int j = 0; j < 2; j++)
            cp16(sA0 + so + j * 64 * AW * 2, gA + s * BK + (size_t)j * 64 * KD);
#pragma unroll
        for (int j = 0; j < 4; j++)
            cp16(sB0 + so + j * 64 * AW * 2, gB + s * BK + (size_t)j * 64 * KD);
        cp_commit();
    }

    // ldmatrix lane addressing
    int li = lane & 7, qq = lane >> 3;           // quadrant 0..3
    uint32_t aAddr[4], bAddr[4];
#pragma unroll
    for (int mt = 0; mt < 4; mt++) {
        int row = wr * 64 + mt * 16 + (qq & 1) * 8 + li;
        int ho  = (qq >> 1) * 8;
        aAddr[mt] = (uint32_t)__cvta_generic_to_shared(smh + row * AW + ho);
    }
#pragma unroll
    for (int p = 0; p < 4; p++) {
        int row = wc * 64 + p * 16 + (qq >> 1) * 8 + li;
        int ho  = (qq & 1) * 8;
        bAddr[p] = (uint32_t)__cvta_generic_to_shared(smh + A_HALFS + row * AW + ho);
    }

    float acc[4][8][4];
#pragma unroll
    for (int mt = 0; mt < 4; mt++)
#pragma unroll
        for (int nt = 0; nt < 8; nt++)
#pragma unroll
            for (int v = 0; v < 4; v++) acc[mt][nt][v] = 0.0f;

    for (int c = 0; c < KCH; c++) {
        cp_wait2();
        __syncthreads();

        int c3 = c + 3;
        if (c3 < KCH) {
            uint32_t so = (uint32_t)((c3 & 3) * STAGE_BYTES);
#pragma unroll
            for (int j = 0; j < 2; j++)
                cp16(sA0 + so + j * 64 * AW * 2, gA + c3 * BK + (size_t)j * 64 * KD);
#pragma unroll
            for (int j = 0; j < 4; j++)
                cp16(sB0 + so + j * 64 * AW * 2, gB + c3 * BK + (size_t)j * 64 * KD);
        }
        cp_commit();

        uint32_t stby = (uint32_t)((c & 3) * STAGE_BYTES);
#pragma unroll
        for (int ks = 0; ks < 2; ks++) {
            uint32_t kb = stby + ks * 32;        // 16 halfs = 32B
            uint32_t af[4][4], bf[8][2];
#pragma unroll
            for (int mt = 0; mt < 4; mt++)
                ldsm4(af[mt][0], af[mt][1], af[mt][2], af[mt][3], aAddr[mt] + kb);
#pragma unroll
            for (int p = 0; p < 4; p++) {
                uint32_t r0, r1, r2, r3;
                ldsm4(r0, r1, r2, r3, bAddr[p] + kb);
                bf[2 * p][0] = r0;     bf[2 * p][1] = r1;
                bf[2 * p + 1][0] = r2; bf[2 * p + 1][1] = r3;
            }
#pragma unroll
            for (int mt = 0; mt < 4; mt++)
#pragma unroll
                for (int nt = 0; nt < 8; nt++)
                    mma_f16(acc[mt][nt], af[mt], bf[nt]);
        }
    }

    __syncthreads();
#pragma unroll
    for (int nt = 0; nt < 8; nt++) {
        int col = mBase + wc * 64 + nt * 8 + 2 * tig;
        float2 bv = *reinterpret_cast<const float2*>(bias + col);
#pragma unroll
        for (int mt = 0; mt < 4; mt++) {
            int r0 = bsBase + wr * 64 + mt * 16 + g;
            float2 o0, o1;
            o0.x = acc[mt][nt][0] + bv.x;
            o0.y = acc[mt][nt][1] + bv.y;
            o1.x = acc[mt][nt][2] + bv.x;
            o1.y = acc[mt][nt][3] + bv.y;
            *reinterpret_cast<float2*>(out + (size_t)r0 * MD + col) = o0;
            *reinterpret_cast<float2*>(out + (size_t)(r0 + 8) * MD + col) = o1;
        }
    }
}

// ---------------- launch ----------------
extern "C" void kernel_launch(void* const* d_in, const int* in_sizes, int n_in,
                              void* d_out, int out_size) {
    const float* x    = (const float*)d_in[0];
    const float* dna  = (const float*)d_in[1];
    const float* bias = (const float*)d_in[2];
    const int*   hd   = (const int*)d_in[3];

    lut_kernel<<<(NLUT + 1 + 255) / 256, 256>>>(dna);
    sum_kernel<<<8192, 256>>>(hd);
    wgen_kernel<<<8192, 256>>>(hd);
    convx_kernel<<<4096, 256>>>(x);

    cudaFuncSetAttribute(gemm_f16, cudaFuncAttributeMaxDynamicSharedMemorySize, SMEM_TOTAL);
    dim3 grid(MD / BN, BSD / BM);   // (16, 64)
    gemm_f16<<<grid, 256, SMEM_TOTAL>>>(bias, (float*)d_out);
}

// round 7
// speedup vs baseline: 2.0797x; 1.2800x over previous
#include <cuda_runtime.h>
#include <cuda_fp16.h>
#include <cstdint>

// ---------------- problem constants ----------------
#define MD   4096
#define KD   4096
#define BSD  8192
#define NTOT 16777216ull
#define NLUT 262144              // 2^18 intervals; d index = d/64 exactly

// ---------------- scratch (device globals) ----------------
__device__ __half  g_wh[(size_t)MD * KD];
__device__ __half  g_xh[(size_t)BSD * KD];
__device__ float   g_lut[NLUT + 1];
__device__ double2 g_part[64];
__device__ float   g_stats[2];
__device__ int     g_counter;

// ---------------- 0) build r(ang) LUT ----------------
__global__ void __launch_bounds__(256) lut_kernel(const float* __restrict__ dna) {
    int i = blockIdx.x * blockDim.x + threadIdx.x;
    if (i > NLUT) return;
    float mp = dna[0], a = dna[1], b = dna[2], n1 = dna[3], n2 = dna[4], n3 = dna[5];
    float span = mp * 2.0f * 3.14159265358979323846f * 0.25f;
    float ang = span * ((float)i / (float)NLUT);
    float sn, cs; sincosf(ang, &sn, &cs);
    float bse = powf(fabsf(cs / a), n2) + powf(fabsf(sn / b), n3);
    g_lut[i] = powf(bse, -1.0f / n1);
}

__device__ __forceinline__ float lut_r(int d) {
    float u = (float)d * (1.0f / 64.0f);
    int i = (int)u;
    i = i < NLUT ? i : NLUT - 1;
    float f = u - (float)i;
    float v0 = g_lut[i], v1 = g_lut[i + 1];
    return v0 + f * (v1 - v0);
}

// ---------------- 1) closed-form stats from LUT ----------------
// hilbert_d is a bijection onto [0,2^24); interval i covers d=64i..64i+63 with
// f = j/64: sum_j f = 31.5, sum_j f^2 = 20.8359375.
__global__ void __launch_bounds__(256) stat_kernel() {
    __shared__ double s1[256], s2[256];
    __shared__ int lastFlag;
    int t = threadIdx.x;
    double s = 0.0, q = 0.0;
    int base = blockIdx.x * (NLUT / 64);            // 4096 intervals per block
    for (int j = t; j < NLUT / 64; j += 256) {
        int i = base + j;
        double v0 = (double)g_lut[i];
        double dv = (double)g_lut[i + 1] - v0;
        s += 64.0 * v0 + 31.5 * dv;
        q += 64.0 * v0 * v0 + 63.0 * v0 * dv + 20.8359375 * dv * dv;
    }
    s1[t] = s; s2[t] = q; __syncthreads();
    for (int o = 128; o > 0; o >>= 1) {
        if (t < o) { s1[t] += s1[t + o]; s2[t] += s2[t + o]; }
        __syncthreads();
    }
    if (t == 0) {
        double2 p; p.x = s1[0]; p.y = s2[0];
        g_part[blockIdx.x] = p;
        __threadfence();
        int old = atomicAdd(&g_counter, 1);
        lastFlag = (old == gridDim.x - 1) ? 1 : 0;
    }
    __syncthreads();
    if (lastFlag) {
        __threadfence();
        double fs = 0.0, fq = 0.0;
        if (t < 64) { double2 p = g_part[t]; fs = p.x; fq = p.y; }
        s1[t] = fs; s2[t] = fq; __syncthreads();
        for (int o = 128; o > 0; o >>= 1) {
            if (t < o) { s1[t] += s1[t + o]; s2[t] += s2[t + o]; }
            __syncthreads();
        }
        if (t == 0) {
            double N = (double)NTOT;
            double mean = s1[0] / N;
            double var  = (s2[0] - s1[0] * s1[0] / N) / (N - 1.0);
            double alpha = (1.0 / 64.0) / (sqrt(var) + 1e-9);
            g_stats[0] = (float)mean;
            g_stats[1] = (float)alpha;
            g_counter = 0;
        }
    }
}

// ---------------- 2) fused prep: w' -> fp16 (blocks 0..8191), x -> fp16 (8192..12287)
__global__ void __launch_bounds__(256) prep_kernel(const int* __restrict__ hd,
                                                   const float* __restrict__ x) {
    int t = threadIdx.x;
    if (blockIdx.x < 8192) {
        float mean = g_stats[0], al = g_stats[1];
        size_t base = (size_t)blockIdx.x * 2048;
#pragma unroll
        for (int j = 0; j < 8; j++) {
            size_t i = base + (size_t)j * 256 + t;
            float r = lut_r(hd[i]);
            g_wh[i] = __float2half_rn((r - mean) * al);
        }
    } else {
        const float4* xi = reinterpret_cast<const float4*>(x);
        uint2* xo = reinterpret_cast<uint2*>(g_xh);
        size_t base = (size_t)(blockIdx.x - 8192) * 2048;
#pragma unroll
        for (int j = 0; j < 8; j++) {
            size_t i = base + (size_t)j * 256 + t;
            float4 v = xi[i];
            __half2 h0 = __floats2half2_rn(v.x, v.y);
            __half2 h1 = __floats2half2_rn(v.z, v.w);
            uint2 o;
            o.x = *reinterpret_cast<uint32_t*>(&h0);
            o.y = *reinterpret_cast<uint32_t*>(&h1);
            xo[i] = o;
        }
    }
}

// ---------------- 3) FP16 mma.sync GEMM, BK=64, 3 stages, frag double-buffer --
#define BM 128
#define BN 256
#define BK 64
#define KCH (KD / BK)              // 64
#define STAGES 3
#define AW 72                      // 64 + 8 pad halfs -> 144B row stride
#define A_HALFS (BM * AW)
#define B_HALFS (BN * AW)
#define STAGE_HALFS (A_HALFS + B_HALFS)        // 27648
#define STAGE_BYTES (STAGE_HALFS * 2)          // 55296
#define SMEM_TOTAL (STAGES * STAGE_BYTES)      // 165888

__device__ __forceinline__ void cp16(uint32_t saddr, const void* gaddr) {
    asm volatile("cp.async.cg.shared.global [%0], [%1], 16;" :: "r"(saddr), "l"(gaddr));
}
__device__ __forceinline__ void cp_commit() {
    asm volatile("cp.async.commit_group;" ::: "memory");
}
__device__ __forceinline__ void cp_wait1() {
    asm volatile("cp.async.wait_group 1;" ::: "memory");
}
__device__ __forceinline__ void ldsm4(uint32_t& r0, uint32_t& r1, uint32_t& r2, uint32_t& r3,
                                      uint32_t addr) {
    asm volatile("ldmatrix.sync.aligned.m8n8.x4.shared.b16 {%0,%1,%2,%3}, [%4];"
                 : "=r"(r0), "=r"(r1), "=r"(r2), "=r"(r3) : "r"(addr));
}
__device__ __forceinline__ void mma_f16(float* d, const uint32_t* a, const uint32_t* b) {
    asm volatile("mma.sync.aligned.m16n8k16.row.col.f32.f16.f16.f32 "
                 "{%0,%1,%2,%3}, {%4,%5,%6,%7}, {%8,%9}, {%0,%1,%2,%3};"
                 : "+f"(d[0]), "+f"(d[1]), "+f"(d[2]), "+f"(d[3])
                 : "r"(a[0]), "r"(a[1]), "r"(a[2]), "r"(a[3]), "r"(b[0]), "r"(b[1]));
}

__global__ void __launch_bounds__(256, 1) gemm_f16(const float* __restrict__ bias,
                                                   float* __restrict__ out) {
    extern __shared__ __half smh[];
    int tid = threadIdx.x, wid = tid >> 5, lane = tid & 31;
    int wr = wid & 1, wc = wid >> 1;
    int g = lane >> 2, tig = lane & 3;
    int mBase  = blockIdx.x * BN;
    int bsBase = blockIdx.y * BM;

    // cp.async staging: rows of 64 halfs = 8 x 16B segs
    int srow = tid >> 3, sseg = tid & 7;            // A: 32-row groups x4; B: x8
    const __half* gA = g_xh + (size_t)(bsBase + srow) * KD + sseg * 8;
    const __half* gB = g_wh + (size_t)(mBase  + srow) * KD + sseg * 8;
    uint32_t sA0 = (uint32_t)__cvta_generic_to_shared(smh + srow * AW + sseg * 8);
    uint32_t sB0 = (uint32_t)__cvta_generic_to_shared(smh + A_HALFS + srow * AW + sseg * 8);

#define ISSUE_STAGE(slot, cc)                                                          \
    do {                                                                               \
        uint32_t so = (uint32_t)((slot) * STAGE_BYTES);                                \
        _Pragma("unroll")                                                              \
        for (int j = 0; j < 4; j++)                                                    \
            cp16(sA0 + so + j * 32 * AW * 2, gA + (cc) * BK + (size_t)j * 32 * KD);    \
        _Pragma("unroll")                                                              \
        for (int j = 0; j < 8; j++)                                                    \
            cp16(sB0 + so + j * 32 * AW * 2, gB + (cc) * BK + (size_t)j * 32 * KD);    \
    } while (0)

    // prologue: stages 0,1
    ISSUE_STAGE(0, 0); cp_commit();
    ISSUE_STAGE(1, 1); cp_commit();

    // ldmatrix lane addressing (qq = 8x8 matrix index)
    int li = lane & 7, qq = lane >> 3;
    uint32_t aAddr[4], bAddr[4];
#pragma unroll
    for (int mt = 0; mt < 4; mt++) {
        int row = wr * 64 + mt * 16 + (qq & 1) * 8 + li;
        aAddr[mt] = (uint32_t)__cvta_generic_to_shared(smh + row * AW + (qq >> 1) * 8);
    }
#pragma unroll
    for (int p = 0; p < 4; p++) {
        int row = wc * 64 + p * 16 + (qq >> 1) * 8 + li;
        bAddr[p] = (uint32_t)__cvta_generic_to_shared(smh + A_HALFS + row * AW + (qq & 1) * 8);
    }

    float acc[4][8][4];
#pragma unroll
    for (int mt = 0; mt < 4; mt++)
#pragma unroll
        for (int nt = 0; nt < 8; nt++)
#pragma unroll
            for (int v = 0; v < 4; v++) acc[mt][nt][v] = 0.0f;

    uint32_t af0[4][4], bf0[8][2], af1[4][4], bf1[8][2];

#define LOADF(AF, BF, kb)                                                              \
    do {                                                                               \
        _Pragma("unroll")                                                              \
        for (int mt = 0; mt < 4; mt++)                                                 \
            ldsm4(AF[mt][0], AF[mt][1], AF[mt][2], AF[mt][3], aAddr[mt] + (kb));       \
        _Pragma("unroll")                                                              \
        for (int p = 0; p < 4; p++) {                                                  \
            uint32_t r0, r1, r2, r3;                                                   \
            ldsm4(r0, r1, r2, r3, bAddr[p] + (kb));                                    \
            BF[2 * p][0] = r0;     BF[2 * p][1] = r1;                                  \
            BF[2 * p + 1][0] = r2; BF[2 * p + 1][1] = r3;                              \
        }                                                                              \
    } while (0)

#define MMAB(AF, BF)                                                                   \
    do {                                                                               \
        _Pragma("unroll")                                                              \
        for (int mt = 0; mt < 4; mt++)                                                 \
            _Pragma("unroll")                                                          \
            for (int nt = 0; nt < 8; nt++)                                             \
                mma_f16(acc[mt][nt], AF[mt], BF[nt]);                                  \
    } while (0)

    for (int c = 0; c < KCH; c++) {
        cp_wait1();
        __syncthreads();
        int c2 = c + 2;
        if (c2 < KCH) ISSUE_STAGE(c2 % STAGES, c2);
        cp_commit();                       // keep group count advancing (empty ok)

        uint32_t st = (uint32_t)((c % STAGES) * STAGE_BYTES);
        LOADF(af0, bf0, st);               // ks 0
        LOADF(af1, bf1, st + 32);          // ks 1
        MMAB(af0, bf0);
        LOADF(af0, bf0, st + 64);          // ks 2 (overlaps MMAs above)
        MMAB(af1, bf1);
        LOADF(af1, bf1, st + 96);          // ks 3
        MMAB(af0, bf0);
        MMAB(af1, bf1);
    }

    __syncthreads();
#pragma unroll
    for (int nt = 0; nt < 8; nt++) {
        int col = mBase + wc * 64 + nt * 8 + 2 * tig;
        float2 bv = *reinterpret_cast<const float2*>(bias + col);
#pragma unroll
        for (int mt = 0; mt < 4; mt++) {
            int r0 = bsBase + wr * 64 + mt * 16 + g;
            float2 o0, o1;
            o0.x = acc[mt][nt][0] + bv.x;
            o0.y = acc[mt][nt][1] + bv.y;
            o1.x = acc[mt][nt][2] + bv.x;
            o1.y = acc[mt][nt][3] + bv.y;
            *reinterpret_cast<float2*>(out + (size_t)r0 * MD + col) = o0;
            *reinterpret_cast<float2*>(out + (size_t)(r0 + 8) * MD + col) = o1;
        }
    }
}

// ---------------- launch ----------------
extern "C" void kernel_launch(void* const* d_in, const int* in_sizes, int n_in,
                              void* d_out, int out_size) {
    const float* x    = (const float*)d_in[0];
    const float* dna  = (const float*)d_in[1];
    const float* bias = (const float*)d_in[2];
    const int*   hd   = (const int*)d_in[3];

    lut_kernel<<<(NLUT + 1 + 255) / 256, 256>>>(dna);
    stat_kernel<<<64, 256>>>();
    prep_kernel<<<12288, 256>>>(hd, x);

    cudaFuncSetAttribute(gemm_f16, cudaFuncAttributeMaxDynamicSharedMemorySize, SMEM_TOTAL);
    dim3 grid(MD / BN, BSD / BM);   // (16, 64)
    gemm_f16<<<grid, 256, SMEM_TOTAL>>>(bias, (float*)d_out);
}

// round 8
// speedup vs baseline: 2.1740x; 1.0454x over previous
#include <cuda_runtime.h>
#include <cuda_fp16.h>
#include <cstdint>

// ---------------- problem constants ----------------
#define MD   4096
#define KD   4096
#define BSD  8192
#define NTOT 16777216ull
#define NLUT 262144              // 2^18 intervals; d index = d/64 exactly

// ---------------- scratch (device globals) ----------------
__device__ __half  g_wh[(size_t)MD * KD];
__device__ __half  g_xh[(size_t)BSD * KD];
__device__ float   g_lut[NLUT + 1];
__device__ double2 g_part[64];
__device__ float   g_stats[2];
__device__ int     g_counter;

// ---------------- 0) build r(ang) LUT ----------------
__global__ void __launch_bounds__(256) lut_kernel(const float* __restrict__ dna) {
    int i = blockIdx.x * blockDim.x + threadIdx.x;
    if (i > NLUT) return;
    float mp = dna[0], a = dna[1], b = dna[2], n1 = dna[3], n2 = dna[4], n3 = dna[5];
    float span = mp * 2.0f * 3.14159265358979323846f * 0.25f;
    float ang = span * ((float)i / (float)NLUT);
    float sn, cs; sincosf(ang, &sn, &cs);
    float bse = powf(fabsf(cs / a), n2) + powf(fabsf(sn / b), n3);
    g_lut[i] = powf(bse, -1.0f / n1);
}

__device__ __forceinline__ float lut_r(int d) {
    float u = (float)d * (1.0f / 64.0f);
    int i = (int)u;
    i = i < NLUT ? i : NLUT - 1;
    float f = u - (float)i;
    float v0 = g_lut[i], v1 = g_lut[i + 1];
    return v0 + f * (v1 - v0);
}

// ---------------- 1) closed-form stats from LUT ----------------
// hilbert_d is a bijection onto [0,2^24); interval i covers d=64i..64i+63,
// f = j/64: sum_j f = 31.5, sum_j f^2 = 20.8359375.
__global__ void __launch_bounds__(256) stat_kernel() {
    __shared__ double s1[256], s2[256];
    __shared__ int lastFlag;
    int t = threadIdx.x;
    double s = 0.0, q = 0.0;
    int base = blockIdx.x * (NLUT / 64);
    for (int j = t; j < NLUT / 64; j += 256) {
        int i = base + j;
        double v0 = (double)g_lut[i];
        double dv = (double)g_lut[i + 1] - v0;
        s += 64.0 * v0 + 31.5 * dv;
        q += 64.0 * v0 * v0 + 63.0 * v0 * dv + 20.8359375 * dv * dv;
    }
    s1[t] = s; s2[t] = q; __syncthreads();
    for (int o = 128; o > 0; o >>= 1) {
        if (t < o) { s1[t] += s1[t + o]; s2[t] += s2[t + o]; }
        __syncthreads();
    }
    if (t == 0) {
        double2 p; p.x = s1[0]; p.y = s2[0];
        g_part[blockIdx.x] = p;
        __threadfence();
        int old = atomicAdd(&g_counter, 1);
        lastFlag = (old == gridDim.x - 1) ? 1 : 0;
    }
    __syncthreads();
    if (lastFlag) {
        __threadfence();
        double fs = 0.0, fq = 0.0;
        if (t < 64) { double2 p = g_part[t]; fs = p.x; fq = p.y; }
        s1[t] = fs; s2[t] = fq; __syncthreads();
        for (int o = 128; o > 0; o >>= 1) {
            if (t < o) { s1[t] += s1[t + o]; s2[t] += s2[t + o]; }
            __syncthreads();
        }
        if (t == 0) {
            double N = (double)NTOT;
            double mean = s1[0] / N;
            double var  = (s2[0] - s1[0] * s1[0] / N) / (N - 1.0);
            double alpha = (1.0 / 64.0) / (sqrt(var) + 1e-9);
            g_stats[0] = (float)mean;
            g_stats[1] = (float)alpha;
            g_counter = 0;
        }
    }
}

// ---------------- 2) fused prep: w' (blocks 0..8191), x (8192..12287) -------
__global__ void __launch_bounds__(256) prep_kernel(const int* __restrict__ hd,
                                                   const float* __restrict__ x) {
    int t = threadIdx.x;
    if (blockIdx.x < 8192) {
        float mean = g_stats[0], al = g_stats[1];
        size_t base = (size_t)blockIdx.x * 2048;
#pragma unroll
        for (int j = 0; j < 8; j++) {
            size_t i = base + (size_t)j * 256 + t;
            float r = lut_r(hd[i]);
            g_wh[i] = __float2half_rn((r - mean) * al);
        }
    } else {
        const float4* xi = reinterpret_cast<const float4*>(x);
        uint2* xo = reinterpret_cast<uint2*>(g_xh);
        size_t base = (size_t)(blockIdx.x - 8192) * 2048;
#pragma unroll
        for (int j = 0; j < 8; j++) {
            size_t i = base + (size_t)j * 256 + t;
            float4 v = xi[i];
            __half2 h0 = __floats2half2_rn(v.x, v.y);
            __half2 h1 = __floats2half2_rn(v.z, v.w);
            uint2 o;
            o.x = *reinterpret_cast<uint32_t*>(&h0);
            o.y = *reinterpret_cast<uint32_t*>(&h1);
            xo[i] = o;
        }
    }
}

// ---------------- 3) FP16 GEMM: 512 thr, 16 warps of 32x64, BK=64, 3 stages --
#define BM 128
#define BN 256
#define BK 64
#define KCH (KD / BK)              // 64
#define STAGES 3
#define AW 72                      // 64 + 8 pad halfs -> 144B row stride
#define A_HALFS (BM * AW)
#define B_HALFS (BN * AW)
#define STAGE_HALFS (A_HALFS + B_HALFS)
#define STAGE_BYTES (STAGE_HALFS * 2)          // 55296
#define SMEM_TOTAL (STAGES * STAGE_BYTES)      // 165888

__device__ __forceinline__ void cp16(uint32_t saddr, const void* gaddr) {
    asm volatile("cp.async.cg.shared.global [%0], [%1], 16;" :: "r"(saddr), "l"(gaddr));
}
__device__ __forceinline__ void cp_commit() {
    asm volatile("cp.async.commit_group;" ::: "memory");
}
__device__ __forceinline__ void cp_wait1() {
    asm volatile("cp.async.wait_group 1;" ::: "memory");
}
__device__ __forceinline__ void ldsm4(uint32_t& r0, uint32_t& r1, uint32_t& r2, uint32_t& r3,
                                      uint32_t addr) {
    asm volatile("ldmatrix.sync.aligned.m8n8.x4.shared.b16 {%0,%1,%2,%3}, [%4];"
                 : "=r"(r0), "=r"(r1), "=r"(r2), "=r"(r3) : "r"(addr));
}
__device__ __forceinline__ void mma_f16(float* d, const uint32_t* a, const uint32_t* b) {
    asm volatile("mma.sync.aligned.m16n8k16.row.col.f32.f16.f16.f32 "
                 "{%0,%1,%2,%3}, {%4,%5,%6,%7}, {%8,%9}, {%0,%1,%2,%3};"
                 : "+f"(d[0]), "+f"(d[1]), "+f"(d[2]), "+f"(d[3])
                 : "r"(a[0]), "r"(a[1]), "r"(a[2]), "r"(a[3]), "r"(b[0]), "r"(b[1]));
}

__global__ void __launch_bounds__(512, 1) gemm_f16(const float* __restrict__ bias,
                                                   float* __restrict__ out) {
    extern __shared__ __half smh[];
    int tid = threadIdx.x, wid = tid >> 5, lane = tid & 31;
    int wr = wid & 3;            // 4 bs-groups of 32
    int wc = wid >> 2;           // 4 m-groups of 64
    int g = lane >> 2, tig = lane & 3;
    int mBase  = blockIdx.x * BN;
    int bsBase = blockIdx.y * BM;

    // cp.async staging for 512 threads: srow 0..63, sseg 0..7
    int srow = tid >> 3, sseg = tid & 7;
    const __half* gA = g_xh + (size_t)(bsBase + srow) * KD + sseg * 8;
    const __half* gB = g_wh + (size_t)(mBase  + srow) * KD + sseg * 8;
    uint32_t sA0 = (uint32_t)__cvta_generic_to_shared(smh + srow * AW + sseg * 8);
    uint32_t sB0 = (uint32_t)__cvta_generic_to_shared(smh + A_HALFS + srow * AW + sseg * 8);

#define ISSUE_STAGE(slot, cc)                                                          \
    do {                                                                               \
        uint32_t so = (uint32_t)((slot) * STAGE_BYTES);                                \
        _Pragma("unroll")                                                              \
        for (int j = 0; j < 2; j++)                                                    \
            cp16(sA0 + so + j * 64 * AW * 2, gA + (cc) * BK + (size_t)j * 64 * KD);    \
        _Pragma("unroll")                                                              \
        for (int j = 0; j < 4; j++)                                                    \
            cp16(sB0 + so + j * 64 * AW * 2, gB + (cc) * BK + (size_t)j * 64 * KD);    \
    } while (0)

    ISSUE_STAGE(0, 0); cp_commit();
    ISSUE_STAGE(1, 1); cp_commit();

    // ldmatrix lane addressing
    int li = lane & 7, qq = lane >> 3;
    uint32_t aAddr[2], bAddr[4];
#pragma unroll
    for (int mt = 0; mt < 2; mt++) {
        int row = wr * 32 + mt * 16 + (qq & 1) * 8 + li;
        aAddr[mt] = (uint32_t)__cvta_generic_to_shared(smh + row * AW + (qq >> 1) * 8);
    }
#pragma unroll
    for (int p = 0; p < 4; p++) {
        int row = wc * 64 + p * 16 + (qq >> 1) * 8 + li;
        bAddr[p] = (uint32_t)__cvta_generic_to_shared(smh + A_HALFS + row * AW + (qq & 1) * 8);
    }

    float acc[2][8][4];
#pragma unroll
    for (int mt = 0; mt < 2; mt++)
#pragma unroll
        for (int nt = 0; nt < 8; nt++)
#pragma unroll
            for (int v = 0; v < 4; v++) acc[mt][nt][v] = 0.0f;

    for (int c = 0; c < KCH; c++) {
        cp_wait1();
        __syncthreads();
        int c2 = c + 2;
        if (c2 < KCH) ISSUE_STAGE(c2 % STAGES, c2);
        cp_commit();

        uint32_t st = (uint32_t)((c % STAGES) * STAGE_BYTES);
#pragma unroll
        for (int ks = 0; ks < 4; ks++) {
            uint32_t kb = st + ks * 32;          // 16 halfs = 32B
            uint32_t af[2][4], bf[8][2];
#pragma unroll
            for (int mt = 0; mt < 2; mt++)
                ldsm4(af[mt][0], af[mt][1], af[mt][2], af[mt][3], aAddr[mt] + kb);
#pragma unroll
            for (int p = 0; p < 4; p++) {
                uint32_t r0, r1, r2, r3;
                ldsm4(r0, r1, r2, r3, bAddr[p] + kb);
                bf[2 * p][0] = r0;     bf[2 * p][1] = r1;
                bf[2 * p + 1][0] = r2; bf[2 * p + 1][1] = r3;
            }
#pragma unroll
            for (int mt = 0; mt < 2; mt++)
#pragma unroll
                for (int nt = 0; nt < 8; nt++)
                    mma_f16(acc[mt][nt], af[mt], bf[nt]);
        }
    }

    __syncthreads();
#pragma unroll
    for (int nt = 0; nt < 8; nt++) {
        int col = mBase + wc * 64 + nt * 8 + 2 * tig;
        float2 bv = *reinterpret_cast<const float2*>(bias + col);
#pragma unroll
        for (int mt = 0; mt < 2; mt++) {
            int r0 = bsBase + wr * 32 + mt * 16 + g;
            float2 o0, o1;
            o0.x = acc[mt][nt][0] + bv.x;
            o0.y = acc[mt][nt][1] + bv.y;
            o1.x = acc[mt][nt][2] + bv.x;
            o1.y = acc[mt][nt][3] + bv.y;
            *reinterpret_cast<float2*>(out + (size_t)r0 * MD + col) = o0;
            *reinterpret_cast<float2*>(out + (size_t)(r0 + 8) * MD + col) = o1;
        }
    }
}

// ---------------- launch ----------------
extern "C" void kernel_launch(void* const* d_in, const int* in_sizes, int n_in,
                              void* d_out, int out_size) {
    const float* x    = (const float*)d_in[0];
    const float* dna  = (const float*)d_in[1];
    const float* bias = (const float*)d_in[2];
    const int*   hd   = (const int*)d_in[3];

    lut_kernel<<<(NLUT + 1 + 255) / 256, 256>>>(dna);
    stat_kernel<<<64, 256>>>();
    prep_kernel<<<12288, 256>>>(hd, x);

    cudaFuncSetAttribute(gemm_f16, cudaFuncAttributeMaxDynamicSharedMemorySize, SMEM_TOTAL);
    dim3 grid(MD / BN, BSD / BM);   // (16, 64)
    gemm_f16<<<grid, 512, SMEM_TOTAL>>>(bias, (float*)d_out);
}